// round 17
// baseline (speedup 1.0000x reference)
#include <cuda_runtime.h>
#include <cuda_fp16.h>

typedef unsigned short u16;
typedef unsigned int   u32;

#define B_   2
#define S_   2048
#define D_   4096
#define HQ   32
#define HKV  8
#define HD   128
#define GRP  4
#define MR   (B_*S_)   // 4096

// ---------------- scratch (__device__ globals; no runtime allocation) -------
__device__ u16 g_x16[(size_t)MR*D_];                 // fp16 x
__device__ u16 g_qwt_h[(size_t)D_*D_];               // [N,K] fp16 (via conv, natural [K,N] NOT used; see tsplit note)
__device__ u16 g_kwt_h[(size_t)1024*D_],   g_kwt_l[(size_t)1024*D_];
__device__ u16 g_owt_h[(size_t)D_*D_];
__device__ u16 g_vwt_h[(size_t)1024*D_];
__device__ u16 g_qh[(size_t)MR*D_];                  // rope'd Q fp16
__device__ u16 g_kh[(size_t)MR*HKV*HD];              // rope'd K fp16
__device__ u16 g_vth[(size_t)B_*HKV*HD*S_];          // V^T fp16 [b,h,d,s]
__device__ u16 g_ao[(size_t)MR*D_];                  // fp16 attn out

// ---------------------------------------------------------------------------
__device__ __forceinline__ void split2(float v, u16& h, u16& l) {
    __half hb = __float2half_rn(v);
    float r = v - __half2float(hb);
    h = __half_as_ushort(hb);
    l = __half_as_ushort(__float2half_rn(r));
}
__device__ __forceinline__ u16 h16(float v) {
    return __half_as_ushort(__float2half_rn(v));
}

__device__ __forceinline__ u32 smem_u32(const void* p) {
    u32 a;
    asm("{ .reg .u64 t; cvta.to.shared.u64 t, %1; cvt.u32.u64 %0, t; }" : "=r"(a) : "l"(p));
    return a;
}

__device__ __forceinline__ void cp16(u32 sdst, const void* gsrc) {
    asm volatile("cp.async.cg.shared.global [%0], [%1], 16;\n" :: "r"(sdst), "l"(gsrc));
}
#define CP_COMMIT()  asm volatile("cp.async.commit_group;" ::: "memory")
#define CP_WAIT2()   asm volatile("cp.async.wait_group 2;" ::: "memory")
#define CP_WAIT1()   asm volatile("cp.async.wait_group 1;" ::: "memory")
#define CP_WAIT0()   asm volatile("cp.async.wait_group 0;" ::: "memory")

__device__ __forceinline__ void ldsm4(u32* r, u32 addr) {
    asm volatile("ldmatrix.sync.aligned.m8n8.x4.shared.b16 {%0,%1,%2,%3}, [%4];"
        : "=r"(r[0]), "=r"(r[1]), "=r"(r[2]), "=r"(r[3]) : "r"(addr));
}

__device__ __forceinline__ void mma16816(float* d, const u32* a, const u32* b) {
    asm volatile(
        "mma.sync.aligned.m16n8k16.row.col.f32.f16.f16.f32 "
        "{%0,%1,%2,%3}, {%4,%5,%6,%7}, {%8,%9}, {%0,%1,%2,%3};\n"
        : "+f"(d[0]), "+f"(d[1]), "+f"(d[2]), "+f"(d[3])
        : "r"(a[0]), "r"(a[1]), "r"(a[2]), "r"(a[3]), "r"(b[0]), "r"(b[1]));
}

// ---------------------------------------------------------------------------
// GEMM mainloop, single fp16 A. BLO=true: d += A@(Bh+Bl)^T ; false: A@Bh^T.
// 128 x 128 CTA tile, BK=64, 2-stage cp.async, SW128 swizzle.
// ---------------------------------------------------------------------------
template<bool BLO>
__device__ __forceinline__ void gemm_core2(
    u32 sbase,
    const u16* __restrict__ Ap,
    const u16* __restrict__ Bph, const u16* __restrict__ Bpl,
    int lda, int ldb, int m0, int n0, int K,
    float (&d)[4][4][4])
{
    constexpr int NT = 128, NJ = 4;
    constexpr int STG = 16384 + (BLO ? 2 : 1) * NT * 128;

    int tid = threadIdx.x, wid = tid >> 5, lane = tid & 31;
    int wx = wid & 3, wy = wid >> 2;

    int aRow = ((lane >> 3) & 1) * 8 + (lane & 7);
    int aKu  = lane >> 4;
    u32 aBase[4]; int aSw[4];
    #pragma unroll
    for (int mi = 0; mi < 4; mi++) {
        int r = wy * 64 + mi * 16 + aRow;
        aBase[mi] = (u32)(r * 128); aSw[mi] = r & 7;
    }
    int bRow = (lane >> 4) * 8 + (lane & 7);
    int bKu  = (lane >> 3) & 1;
    u32 bBase[NJ / 2]; int bSw[NJ / 2];
    #pragma unroll
    for (int p = 0; p < NJ / 2; p++) {
        int r = wx * 32 + p * 16 + bRow;
        bBase[p] = (u32)(r * 128); bSw[p] = r & 7;
    }

    int nch = K >> 6;

    auto prefetch = [&](int c, int s) {
        u32 st = sbase + s * STG;
        int k0 = c << 6;
        constexpr int TOT = (128 + (BLO ? 2 : 1) * NT) * 8;
        #pragma unroll
        for (int u0 = 0; u0 < TOT; u0 += 256) {
            int u = u0 + tid;
            int row, c16;
            const u16* gp;
            u32 abase;
            if (u0 < 1024) {
                row = (u >> 3) & 127; c16 = u & 7;
                gp = Ap + (long)(m0 + row) * lda + k0 + c16 * 8;
                abase = st;
            } else {
                int v = u - 1024;
                row = (v >> 3) & (NT - 1); c16 = v & 7;
                bool lo = BLO && (v >= NT * 8);
                gp = (lo ? Bpl : Bph) + (long)(n0 + row) * ldb + k0 + c16 * 8;
                abase = st + 16384u + (lo ? (u32)(NT * 128) : 0u);
            }
            u32 so = abase + (u32)(row * 128) + ((u32)(c16 ^ (row & 7)) << 4);
            cp16(so, gp);
        }
    };

    prefetch(0, 0);
    CP_COMMIT();

    for (int c = 0; c < nch; c++) {
        if (c + 1 < nch) { prefetch(c + 1, (c + 1) & 1); CP_COMMIT(); CP_WAIT1(); }
        else             { CP_WAIT0(); }
        __syncthreads();

        u32 st = sbase + (c & 1) * STG;
        u32 sA_ = st, sBh_ = st + 16384, sBl_ = st + 16384 + NT * 128;

        #pragma unroll
        for (int kk = 0; kk < 4; kk++) {
            int kuA = kk * 2 + aKu;
            int kuB = kk * 2 + bKu;
            u32 ah[4][4], xbh[NJ / 2][4];
            #pragma unroll
            for (int mi = 0; mi < 4; mi++)
                ldsm4(ah[mi], sA_ + aBase[mi] + ((u32)(kuA ^ aSw[mi]) << 4));
            #pragma unroll
            for (int p = 0; p < NJ / 2; p++)
                ldsm4(xbh[p], sBh_ + bBase[p] + ((u32)(kuB ^ bSw[p]) << 4));
            #pragma unroll
            for (int mi = 0; mi < 4; mi++)
                #pragma unroll
                for (int nj = 0; nj < NJ; nj++)
                    mma16816(d[mi][nj], ah[mi], &xbh[nj >> 1][(nj & 1) * 2]);
            if (BLO) {
                u32 xbl[NJ / 2][4];
                #pragma unroll
                for (int p = 0; p < NJ / 2; p++)
                    ldsm4(xbl[p], sBl_ + bBase[p] + ((u32)(kuB ^ bSw[p]) << 4));
                #pragma unroll
                for (int mi = 0; mi < 4; mi++)
                    #pragma unroll
                    for (int nj = 0; nj < NJ; nj++)
                        mma16816(d[mi][nj], ah[mi], &xbl[nj >> 1][(nj & 1) * 2]);
            }
        }
        __syncthreads();
    }
}

// ---------------------------------------------------------------------------
// Merged Q/K/V projection. grid.x: 0-7 K (2-term, heavy-first), 8-39 Q, 40-47 V.
// Q/K: bias + RoPE + fp16 out. V: bias + fp16 out, transposed in smem
// directly to vth [b,hv,d,s].
// ---------------------------------------------------------------------------
__global__ __launch_bounds__(256, 1)
void qkv_gemm(const u16* __restrict__ x16,
              const u16* __restrict__ qwth, const float* __restrict__ qb,
              const u16* __restrict__ kwth, const u16* __restrict__ kwtl, const float* __restrict__ kb,
              const u16* __restrict__ vwth, const float* __restrict__ vb,
              u16* __restrict__ qh, u16* __restrict__ kh,
              u16* __restrict__ vth,
              const float* __restrict__ fc, const float* __restrict__ fs,
              const int* __restrict__ sp)
{
    extern __shared__ __align__(16) char dsm[];
    int nt = blockIdx.x, m0 = blockIdx.y * 128;

    const u16 *Bph = nullptr, *Bpl = nullptr; const float* bias;
    u16* Ch = nullptr;
    int ldc = 0, n0; bool blo; bool isV = false;
    if (nt < 8)       { Bph = kwth; Bpl = kwtl; bias = kb; Ch = kh; ldc = 1024; n0 = nt * 128;        blo = true;  }
    else if (nt < 40) { Bph = qwth;             bias = qb; Ch = qh; ldc = 4096; n0 = (nt - 8) * 128;  blo = false; }
    else              { Bph = vwth;             bias = vb;          isV = true; n0 = (nt - 40) * 128; blo = false; }

    float d[4][4][4];
    #pragma unroll
    for (int i = 0; i < 4; i++)
        #pragma unroll
        for (int j = 0; j < 4; j++)
            #pragma unroll
            for (int q = 0; q < 4; q++) d[i][j][q] = 0.f;

    if (blo) gemm_core2<true >(smem_u32(dsm), x16, Bph, Bpl, D_, D_, m0, n0, D_, d);
    else     gemm_core2<false>(smem_u32(dsm), x16, Bph, Bpl, D_, D_, m0, n0, D_, d);

    int tid = threadIdx.x, wid = tid >> 5, lane = tid & 31;
    int wx = wid & 3, wy = wid >> 2;
    int g = lane >> 2, tg = lane & 3;

    if (isV) {
        u16* U = (u16*)dsm;
        #pragma unroll
        for (int mi = 0; mi < 4; mi++) {
            int rl = wy * 64 + mi * 16 + g;
            #pragma unroll
            for (int nj = 0; nj < 4; nj++) {
                int c = n0 + wx * 32 + nj * 8 + tg * 2;
                int dd = c & 127;
                float b0 = bias[c], b1 = bias[c + 1];
                U[dd * 136 + rl]           = h16(d[mi][nj][0] + b0);
                U[(dd + 1) * 136 + rl]     = h16(d[mi][nj][1] + b1);
                U[dd * 136 + rl + 8]       = h16(d[mi][nj][2] + b0);
                U[(dd + 1) * 136 + rl + 8] = h16(d[mi][nj][3] + b1);
            }
        }
        __syncthreads();
        int bb = m0 >> 11;
        int s0 = m0 & (S_ - 1);
        int hv = n0 >> 7;
        u16* dst = vth + ((long)(bb * HKV + hv) * HD) * S_ + s0;
        #pragma unroll
        for (int i0 = 0; i0 < 2048; i0 += 256) {
            int i = i0 + tid;
            int dd = i >> 4, un = i & 15;
            uint4 val = *(uint4*)(U + dd * 136 + un * 8);
            *(uint4*)(dst + (long)dd * S_ + un * 8) = val;
        }
        return;
    }

    int sp0 = *sp;
    #pragma unroll
    for (int mi = 0; mi < 4; mi++) {
        #pragma unroll
        for (int nj = 0; nj < 4; nj++) {
            int r = m0 + wy * 64 + mi * 16 + g;
            int c = n0 + wx * 32 + nj * 8 + tg * 2;
            float b0 = bias[c], b1 = bias[c + 1];
            float v0 = d[mi][nj][0] + b0, v1 = d[mi][nj][1] + b1;
            float v2 = d[mi][nj][2] + b0, v3 = d[mi][nj][3] + b1;
            long o0 = (long)r * ldc + c;
            long o1 = o0 + 8L * ldc;
            int i_ = (c & 127) >> 1;
            int s0 = (r & (S_ - 1)) + sp0;
            int s8 = ((r + 8) & (S_ - 1)) + sp0;
            float c0f = fc[s0 * 64 + i_], s0f = fs[s0 * 64 + i_];
            float c8f = fc[s8 * 64 + i_], s8f = fs[s8 * 64 + i_];
            float r0 = v0 * c0f - v1 * s0f, r1 = v0 * s0f + v1 * c0f;
            float r2 = v2 * c8f - v3 * s8f, r3 = v2 * s8f + v3 * c8f;
            *(u32*)&Ch[o0] = (u32)h16(r0) | ((u32)h16(r1) << 16);
            *(u32*)&Ch[o1] = (u32)h16(r2) | ((u32)h16(r3) << 16);
        }
    }
}

// ---------------------------------------------------------------------------
// Output projection: out = AO(fp16) @ owh^T, 1-term, NT=128. fp32 out.
// ---------------------------------------------------------------------------
__global__ __launch_bounds__(256, 1)
void oproj_gemm(const u16* __restrict__ Ap,
                const u16* __restrict__ Bgh,
                float* __restrict__ Cf)
{
    extern __shared__ __align__(16) char dsm[];
    int m0 = blockIdx.y * 128, n0 = blockIdx.x * 128;

    float d[4][4][4];
    #pragma unroll
    for (int i = 0; i < 4; i++)
        #pragma unroll
        for (int j = 0; j < 4; j++)
            #pragma unroll
            for (int q = 0; q < 4; q++) d[i][j][q] = 0.f;

    gemm_core2<false>(smem_u32(dsm), Ap, Bgh, nullptr, D_, D_, m0, n0, D_, d);

    int tid = threadIdx.x, wid = tid >> 5, lane = tid & 31;
    int wx = wid & 3, wy = wid >> 2;
    int g = lane >> 2, tg = lane & 3;

    #pragma unroll
    for (int mi = 0; mi < 4; mi++) {
        #pragma unroll
        for (int nj = 0; nj < 4; nj++) {
            int r = m0 + wy * 64 + mi * 16 + g;
            int c = n0 + wx * 32 + nj * 8 + tg * 2;
            long o0 = (long)r * D_ + c;
            long o1 = o0 + 8L * D_;
            *(float2*)&Cf[o0] = make_float2(d[mi][nj][0], d[mi][nj][1]);
            *(float2*)&Cf[o1] = make_float2(d[mi][nj][2], d[mi][nj][3]);
        }
    }
}

// ---------------------------------------------------------------------------
// Fused FlashAttention, 64-wide chunks, 2 CTAs/SM (103.9 KB smem):
// S = alpha*Qh@Kh^T (1-term), online softmax, O = Ph@Vh (1-term).
// Grid: (head, m-rank heavy-first) -> global LPT.
// ---------------------------------------------------------------------------
#define FA_Q    0                   // 32 KB (2 cc x 16 KB)
#define FA_K    32768               // 2 stages x 16 KB
#define FA_V    65536               // 16 KB
#define FA_P    81920               // 16 KB
#define FA_ST   98304
#define FA_SMEM (98304 + 5632)

__global__ __launch_bounds__(256, 2)
void fa_fused(const u16* __restrict__ Qh,
              const u16* __restrict__ Kh,
              const u16* __restrict__ Vth,
              u16* __restrict__ Ao, float alpha)
{
    extern __shared__ __align__(16) char dsm[];
    u32 sbase = smem_u32(dsm);
    float* m_run = (float*)(dsm + FA_ST);
    float* l_run = m_run + 128;
    float* fch   = m_run + 256;
    float* mpart = m_run + 384;
    float* lpart = m_run + 896;

    int m0 = (int)(gridDim.y - 1 - blockIdx.y) * 128;     // LPT heavy-first
    int z = blockIdx.x, b = z / HQ, h = z - b * HQ;

    const u16* Qph = Qh + ((long)b * S_ + m0) * D_ + h * HD;
    const u16* Kph = Kh + (long)b * S_ * 1024 + (h / GRP) * HD;
    const u16* Vph = Vth + ((long)b * HKV + (h / GRP)) * (long)HD * S_;

    int tid = threadIdx.x, wid = tid >> 5, lane = tid & 31;
    int wx = wid & 3, wy = wid >> 2;
    int g = lane >> 2, tg = lane & 3;

    if (tid < 128) { m_run[tid] = -1e30f; l_run[tid] = 0.f; }

    int aRow = ((lane >> 3) & 1) * 8 + (lane & 7);
    int aKu  = lane >> 4;
    u32 aBase[4]; int aSw[4];
    #pragma unroll
    for (int mi = 0; mi < 4; mi++) {
        int rr = wy * 64 + mi * 16 + aRow;
        aBase[mi] = (u32)(rr * 128); aSw[mi] = rr & 7;
    }
    int bRow = (lane >> 4) * 8 + (lane & 7);
    int bKu  = (lane >> 3) & 1;
    u32 bBaseS = (u32)((wx * 16 + bRow) * 128); int bSwS = bRow & 7;
    u32 bBaseV[2]; int bSwV[2];
    #pragma unroll
    for (int p = 0; p < 2; p++) {
        int rr = wx * 32 + p * 16 + bRow;
        bBaseV[p] = (u32)(rr * 128); bSwV[p] = rr & 7;
    }

    float d_o[4][4][4];
    #pragma unroll
    for (int i = 0; i < 4; i++)
        #pragma unroll
        for (int j = 0; j < 4; j++)
            #pragma unroll
            for (int q = 0; q < 4; q++) d_o[i][j][q] = 0.f;

    int nch = (m0 + 128) >> 6;

    auto qfetch = [&]() {
        #pragma unroll
        for (int u0 = 0; u0 < 2048; u0 += 256) {
            int u = u0 + tid;
            int cc = u >> 10, v = u & 1023;
            int row = v >> 3, c16 = v & 7;
            const u16* gp = Qph + (long)row * D_ + cc * 64 + c16 * 8;
            u32 so = sbase + FA_Q + (u32)cc * 16384
                   + (u32)(row * 128) + ((u32)(c16 ^ (row & 7)) << 4);
            cp16(so, gp);
        }
    };
    auto kfetch = [&](int c, int s) {
        int j0 = c << 6;
        #pragma unroll
        for (int u0 = 0; u0 < 1024; u0 += 256) {
            int u = u0 + tid;
            int cc = u >> 9, v = u & 511;
            int row = v >> 3, c16 = v & 7;
            const u16* gp = Kph + (long)(j0 + row) * 1024 + cc * 64 + c16 * 8;
            u32 so = sbase + FA_K + (u32)s * 16384 + (u32)cc * 8192
                   + (u32)(row * 128) + ((u32)(c16 ^ (row & 7)) << 4);
            cp16(so, gp);
        }
    };
    auto vfetch = [&](int c) {
        int j0 = c << 6;
        #pragma unroll
        for (int u0 = 0; u0 < 1024; u0 += 256) {
            int u = u0 + tid;
            int row = u >> 3, c16 = u & 7;
            const u16* gp = Vph + (long)row * S_ + j0 + c16 * 8;
            u32 so = sbase + FA_V
                   + (u32)(row * 128) + ((u32)(c16 ^ (row & 7)) << 4);
            cp16(so, gp);
        }
    };

    qfetch();
    CP_COMMIT();
    kfetch(0, 0);
    CP_COMMIT();

    for (int c = 0; c < nch; c++) {
        int j0 = c << 6;
        bool hasNext = (c + 1 < nch);

        vfetch(c); CP_COMMIT();
        if (hasNext) { kfetch(c + 1, (c + 1) & 1); CP_COMMIT(); }

        if (hasNext) CP_WAIT2(); else CP_WAIT1();
        __syncthreads();

        // ---- S = Qh @ Kh^T (1 term) ----
        float d_s[4][2][4];
        #pragma unroll
        for (int i = 0; i < 4; i++)
            #pragma unroll
            for (int j = 0; j < 2; j++)
                #pragma unroll
                for (int q = 0; q < 4; q++) d_s[i][j][q] = 0.f;

        u32 kst = sbase + FA_K + (u32)(c & 1) * 16384;
        #pragma unroll
        for (int cc = 0; cc < 2; cc++) {
            u32 sQ_ = sbase + FA_Q + (u32)cc * 16384;
            u32 sK_ = kst + (u32)cc * 8192;
            #pragma unroll
            for (int kk = 0; kk < 4; kk++) {
                int kuA = kk * 2 + aKu;
                int kuB = kk * 2 + bKu;
                u32 ah[4][4], xb[4];
                #pragma unroll
                for (int mi = 0; mi < 4; mi++)
                    ldsm4(ah[mi], sQ_ + aBase[mi] + ((u32)(kuA ^ aSw[mi]) << 4));
                ldsm4(xb, sK_ + bBaseS + ((u32)(kuB ^ bSwS) << 4));
                #pragma unroll
                for (int mi = 0; mi < 4; mi++)
                    #pragma unroll
                    for (int nj = 0; nj < 2; nj++)
                        mma16816(d_s[mi][nj], ah[mi], &xb[nj * 2]);
            }
        }

        // ---- mask + alpha + chunk row-max ----
        bool domask = (c >= nch - 2);
        #pragma unroll
        for (int mi = 0; mi < 4; mi++) {
            int rl0 = wy * 64 + mi * 16 + g;
            int grow0 = m0 + rl0, grow8 = grow0 + 8;
            float mx0 = -1e30f, mx8 = -1e30f;
            #pragma unroll
            for (int nj = 0; nj < 2; nj++) {
                #pragma unroll
                for (int e = 0; e < 2; e++) {
                    int gc = j0 + wx * 16 + nj * 8 + tg * 2 + e;
                    float v0 = d_s[mi][nj][e] * alpha;
                    float v8 = d_s[mi][nj][2 + e] * alpha;
                    if (domask) {
                        if (gc > grow0) v0 = -1e30f;
                        if (gc > grow8) v8 = -1e30f;
                    }
                    d_s[mi][nj][e] = v0; d_s[mi][nj][2 + e] = v8;
                    mx0 = fmaxf(mx0, v0); mx8 = fmaxf(mx8, v8);
                }
            }
            mx0 = fmaxf(mx0, __shfl_xor_sync(0xffffffffu, mx0, 1));
            mx0 = fmaxf(mx0, __shfl_xor_sync(0xffffffffu, mx0, 2));
            mx8 = fmaxf(mx8, __shfl_xor_sync(0xffffffffu, mx8, 1));
            mx8 = fmaxf(mx8, __shfl_xor_sync(0xffffffffu, mx8, 2));
            if (tg == 0) {
                mpart[wx * 128 + rl0] = mx0;
                mpart[wx * 128 + rl0 + 8] = mx8;
            }
        }
        __syncthreads();

        if (tid < 128) {
            float mc = fmaxf(fmaxf(mpart[tid], mpart[128 + tid]),
                             fmaxf(mpart[256 + tid], mpart[384 + tid]));
            float mo = m_run[tid];
            float mn = fmaxf(mo, mc);
            fch[tid] = __expf(mo - mn);
            m_run[tid] = mn;
        }
        __syncthreads();

        #pragma unroll
        for (int mi = 0; mi < 4; mi++) {
            int rl = wy * 64 + mi * 16 + g;
            float f0 = fch[rl], f8 = fch[rl + 8];
            #pragma unroll
            for (int nj = 0; nj < 4; nj++) {
                d_o[mi][nj][0] *= f0; d_o[mi][nj][1] *= f0;
                d_o[mi][nj][2] *= f8; d_o[mi][nj][3] *= f8;
            }
        }

        // ---- P = exp(S - m), fp16, store to smem; partial sums ----
        #pragma unroll
        for (int mi = 0; mi < 4; mi++) {
            int rl0 = wy * 64 + mi * 16 + g;
            float mrow0 = m_run[rl0], mrow8 = m_run[rl0 + 8];
            float s0 = 0.f, s8 = 0.f;
            #pragma unroll
            for (int nj = 0; nj < 2; nj++) {
                float p00 = __expf(d_s[mi][nj][0] - mrow0);
                float p01 = __expf(d_s[mi][nj][1] - mrow0);
                float p80 = __expf(d_s[mi][nj][2] - mrow8);
                float p81 = __expf(d_s[mi][nj][3] - mrow8);
                s0 += p00 + p01; s8 += p80 + p81;
                int cl = wx * 16 + nj * 8 + tg * 2;
                u32 u0 = (u32)(((cl >> 3) ^ (rl0 & 7)) << 4) + (u32)((cl & 7) * 2);
                u32 u8 = (u32)(((cl >> 3) ^ ((rl0 + 8) & 7)) << 4) + (u32)((cl & 7) * 2);
                *(u32*)(dsm + FA_P + rl0 * 128 + u0) =
                    (u32)h16(p00) | ((u32)h16(p01) << 16);
                *(u32*)(dsm + FA_P + (rl0 + 8) * 128 + u8) =
                    (u32)h16(p80) | ((u32)h16(p81) << 16);
            }
            s0 += __shfl_xor_sync(0xffffffffu, s0, 1);
            s0 += __shfl_xor_sync(0xffffffffu, s0, 2);
            s8 += __shfl_xor_sync(0xffffffffu, s8, 1);
            s8 += __shfl_xor_sync(0xffffffffu, s8, 2);
            if (tg == 0) {
                lpart[wx * 128 + rl0] = s0;
                lpart[wx * 128 + rl0 + 8] = s8;
            }
        }

        if (hasNext) CP_WAIT1(); else CP_WAIT0();
        __syncthreads();

        if (tid < 128) {
            float sum = lpart[tid] + lpart[128 + tid] + lpart[256 + tid] + lpart[384 + tid];
            l_run[tid] = l_run[tid] * fch[tid] + sum;
        }

        // ---- O += Ph @ Vh (1 term) ----
        u32 sP = sbase + FA_P;
        u32 sV = sbase + FA_V;
        #pragma unroll
        for (int kk = 0; kk < 4; kk++) {
            int kuA = kk * 2 + aKu;
            int kuB = kk * 2 + bKu;
            u32 ah[4][4], xb[2][4];
            #pragma unroll
            for (int mi = 0; mi < 4; mi++)
                ldsm4(ah[mi], sP + aBase[mi] + ((u32)(kuA ^ aSw[mi]) << 4));
            #pragma unroll
            for (int p = 0; p < 2; p++)
                ldsm4(xb[p], sV + bBaseV[p] + ((u32)(kuB ^ bSwV[p]) << 4));
            #pragma unroll
            for (int mi = 0; mi < 4; mi++)
                #pragma unroll
                for (int nj = 0; nj < 4; nj++)
                    mma16816(d_o[mi][nj], ah[mi], &xb[nj >> 1][(nj & 1) * 2]);
        }
        __syncthreads();
    }

    // epilogue: divide by l, fp16-truncate, store AO
    #pragma unroll
    for (int mi = 0; mi < 4; mi++) {
        int rl = wy * 64 + mi * 16 + g;
        float i0 = 1.0f / l_run[rl];
        float i8 = 1.0f / l_run[rl + 8];
        #pragma unroll
        for (int nj = 0; nj < 4; nj++) {
            int cc = wx * 32 + nj * 8 + tg * 2;
            long o0 = ((long)b * S_ + m0 + rl) * D_ + h * HD + cc;
            long o1 = o0 + 8L * D_;
            *(u32*)&Ao[o0] = (u32)h16(d_o[mi][nj][0] * i0)
                           | ((u32)h16(d_o[mi][nj][1] * i0) << 16);
            *(u32*)&Ao[o1] = (u32)h16(d_o[mi][nj][2] * i8)
                           | ((u32)h16(d_o[mi][nj][3] * i8) << 16);
        }
    }
}

// ---------------------------------------------------------------------------
// Consolidated fp32 -> fp16 conversion for x, qw^T target, vw, ow (flat index,
// segment dispatch). qw/ow/vw are converted via transpose below; this kernel
// handles x plus the three weight TRANSPOSES' sources are handled by tsplit,
// so here: only x is linear; weights are handled in tsplit. To still save
// launches, this kernel performs x-convert AND feeds nothing else.
// (Kept flat-segmented for the three natural-layout conversions that tsplit
// replaces: qw^T, vw^T, ow^T are transposes, so they stay in tsplit, but the
// three tsplit calls are merged into ONE launch via grid.z dispatch below.)
// ---------------------------------------------------------------------------
__global__ void conv_h(const float* __restrict__ in, u16* __restrict__ oh, long n)
{
    long i = blockIdx.x * 256L + threadIdx.x;
    if (i < n) oh[i] = h16(in[i]);
}

// merged transpose: grid.z selects {0: qw(128x128 grid), 1: ow, 2: vw, 3: kw-split}
__global__ void tsplit_all(const float* __restrict__ qw, u16* __restrict__ qwt,
                           const float* __restrict__ ow, u16* __restrict__ owt,
                           const float* __restrict__ vw, u16* __restrict__ vwt,
                           const float* __restrict__ kw, u16* __restrict__ kwth,
                           u16* __restrict__ kwtl)
{
    __shared__ float t[32][33];
    int zz = blockIdx.z;
    const float* in; u16 *oh, *ol = nullptr; int ldin, ldout; bool writeLo = false;
    if (zz == 0)      { in = qw; oh = qwt; ldin = D_;   ldout = D_; }
    else if (zz == 1) { in = ow; oh = owt; ldin = D_;   ldout = D_; }
    else if (zz == 2) { in = vw; oh = vwt; ldin = 1024; ldout = D_; }
    else              { in = kw; oh = kwth; ol = kwtl; ldin = 1024; ldout = D_; writeLo = true; }

    int c0 = blockIdx.x * 32, r0 = blockIdx.y * 32;
    if (zz >= 2 && c0 >= 1024) return;   // vw/kw have only 1024 columns

    #pragma unroll
    for (int i = 0; i < 4; i++)
        t[threadIdx.y + i * 8][threadIdx.x] =
            in[(long)(r0 + threadIdx.y + i * 8) * ldin + c0 + threadIdx.x];
    __syncthreads();
    #pragma unroll
    for (int i = 0; i < 4; i++) {
        int orow = c0 + threadIdx.y + i * 8;
        int oc = r0 + threadIdx.x;
        float v = t[threadIdx.x][threadIdx.y + i * 8];
        long o = (long)orow * ldout + oc;
        if (writeLo) {
            u16 hh2, ll;
            split2(v, hh2, ll);
            oh[o] = hh2; ol[o] = ll;
        } else {
            oh[o] = h16(v);
        }
    }
}

// ---------------------------------------------------------------------------
extern "C" void kernel_launch(void* const* d_in, const int* in_sizes, int n_in,
                              void* d_out, int out_size)
{
    const float* x  = (const float*)d_in[0];
    const float* fc = (const float*)d_in[1];
    const float* fs = (const float*)d_in[2];
    const float* qw = (const float*)d_in[3];
    const float* qb = (const float*)d_in[4];
    const float* kw = (const float*)d_in[5];
    const float* kb = (const float*)d_in[6];
    const float* vw = (const float*)d_in[7];
    const float* vb = (const float*)d_in[8];
    const float* ow = (const float*)d_in[9];
    const int*   sp = (const int*)d_in[10];
    float* out = (float*)d_out;

    u16 *x16, *qwth, *kwth, *kwtl, *vwth, *owth;
    u16 *qh, *kh, *vth, *ao;
    cudaGetSymbolAddress((void**)&x16, g_x16);
    cudaGetSymbolAddress((void**)&qwth, g_qwt_h);
    cudaGetSymbolAddress((void**)&kwth, g_kwt_h); cudaGetSymbolAddress((void**)&kwtl, g_kwt_l);
    cudaGetSymbolAddress((void**)&vwth, g_vwt_h);
    cudaGetSymbolAddress((void**)&owth, g_owt_h);
    cudaGetSymbolAddress((void**)&qh, g_qh);
    cudaGetSymbolAddress((void**)&kh, g_kh);
    cudaGetSymbolAddress((void**)&vth, g_vth);
    cudaGetSymbolAddress((void**)&ao, g_ao);

    const int SM_QKV = 2 * (16384 + 2 * 128 * 128);   // 98304 (K-path stages)
    const int SM_O   = 2 * (16384 + 1 * 128 * 128);   // 65536
    cudaFuncSetAttribute((const void*)qkv_gemm,
                         cudaFuncAttributeMaxDynamicSharedMemorySize, SM_QKV);
    cudaFuncSetAttribute((const void*)oproj_gemm,
                         cudaFuncAttributeMaxDynamicSharedMemorySize, SM_O);
    cudaFuncSetAttribute((const void*)fa_fused,
                         cudaFuncAttributeMaxDynamicSharedMemorySize, FA_SMEM);

    // 1) converts: x -> fp16 (1 launch); all weight transposes (1 launch)
    conv_h<<<(unsigned)(((long)MR * D_ + 255) / 256), 256>>>(x, x16, (long)MR * D_);
    dim3 tb(32, 8);
    tsplit_all<<<dim3(128, 128, 4), tb>>>(qw, qwth, ow, owth, vw, vwth,
                                          kw, kwth, kwtl);

    // 2) merged Q/K/V projections (V^T written directly from epilogue)
    qkv_gemm<<<dim3(48, 32), 256, SM_QKV>>>(
        x16, qwth, qb, kwth, kwtl, kb, vwth, vb,
        qh, kh, vth, fc, fs, sp);

    // 3) fused attention, 64-chunks, 2 CTAs/SM, LPT grid (head, m-rank)
    fa_fused<<<dim3(B_ * HQ, 16), 256, FA_SMEM>>>(
        qh, kh, vth, ao, 0.08838834764831845f);

    // 4) out = AO @ ow (1-term), NT=128
    oproj_gemm<<<dim3(32, 32), 256, SM_O>>>(ao, owth, out);
}